// round 2
// baseline (speedup 1.0000x reference)
#include <cuda_runtime.h>
#include <math.h>

#define BB   256      // batch
#define SSZ  128      // seq len
#define HHD  512      // hidden
#define G4H  2048     // 4*H
#define KIN  414      // F*N
#define KINP 416      // padded K for float4
#define MTOT (SSZ*BB) // 32768

// ---------------- scratch (device globals; no allocations allowed) ----------
__device__ __align__(256) float g_xs[MTOT * KINP];   // [S*B, 416]
__device__ __align__(256) float g_gx[MTOT * G4H];    // [S*B, 2048]
__device__ __align__(256) float g_h1[MTOT * HHD];    // layer1 hidden seq
__device__ __align__(256) float g_h2[MTOT * HHD];    // layer2 hidden seq
__device__ __align__(256) float g_c [BB * HHD];      // cell state (shared, reset at t==0)

// ---------------- pack: x[B,F,N,S] -> xs[S*B, 416] (k = f*207+n, pad zeros) --
__global__ void pack_x_kernel(const float* __restrict__ x) {
    __shared__ float tile[32][33];
    int b  = blockIdx.x;
    int k0 = blockIdx.y * 32;
    int s0 = blockIdx.z * 32;
    int tx = threadIdx.x, ty = threadIdx.y;  // 32 x 8
    const float* xb = x + (size_t)b * KIN * SSZ;
#pragma unroll
    for (int i = 0; i < 4; i++) {
        int k = k0 + ty + 8 * i;
        if (k < KIN) tile[ty + 8 * i][tx] = xb[k * SSZ + s0 + tx];
    }
    __syncthreads();
#pragma unroll
    for (int i = 0; i < 4; i++) {
        int s = s0 + ty + 8 * i;
        int k = k0 + tx;
        if (k < KINP) {
            float v = (k < KIN) ? tile[tx][ty + 8 * i] : 0.f;
            g_xs[(s * BB + b) * KINP + k] = v;
        }
    }
}

// ---------------- big GEMM: out[m, j] = A[m,:].W[j,:] + bias1[j] + bias2[j] --
// A: [M, lda] (Kpad cols used, Kpad%16==0, lda%4==0), W: [2048, ldw] (Kw real cols)
// out stride = 2048. Tiles 64x64, 256 threads, double buffered.
__global__ __launch_bounds__(256) void gemm_gx_kernel(
    const float* __restrict__ A, int lda, int Kpad,
    const float* __restrict__ W, int ldw, int Kw,
    const float* __restrict__ bias1, const float* __restrict__ bias2,
    float* __restrict__ out)
{
    __shared__ __align__(16) float As[2][16][68];
    __shared__ __align__(16) float Bs[2][16][68];
    int m0 = blockIdx.y * 64;
    int n0 = blockIdx.x * 64;
    int tid = threadIdx.x;
    int tx = tid & 15, ty = tid >> 4;
    int lm = tid >> 2;          // 0..63
    int lk = (tid & 3) * 4;     // 0,4,8,12
    float acc[4][4] = {};
    int nk = Kpad / 16;
    int jb = n0 + lm;

    {   // tile 0
        float4 a4 = *(const float4*)(A + (size_t)(m0 + lm) * lda + lk);
        As[0][lk + 0][lm] = a4.x; As[0][lk + 1][lm] = a4.y;
        As[0][lk + 2][lm] = a4.z; As[0][lk + 3][lm] = a4.w;
#pragma unroll
        for (int q = 0; q < 4; q++) {
            int k = lk + q;
            Bs[0][lk + q][lm] = (k < Kw) ? W[(size_t)jb * ldw + k] : 0.f;
        }
    }
    __syncthreads();
    int buf = 0;
    for (int kt = 0; kt < nk; kt++) {
        float4 a4n; float bn[4];
        bool next = (kt + 1 < nk);
        if (next) {
            int kb = (kt + 1) * 16;
            a4n = *(const float4*)(A + (size_t)(m0 + lm) * lda + kb + lk);
#pragma unroll
            for (int q = 0; q < 4; q++) {
                int k = kb + lk + q;
                bn[q] = (k < Kw) ? W[(size_t)jb * ldw + k] : 0.f;
            }
        }
#pragma unroll
        for (int k = 0; k < 16; k++) {
            float4 av = *(const float4*)&As[buf][k][ty * 4];
            float4 bv = *(const float4*)&Bs[buf][k][tx * 4];
            acc[0][0] += av.x * bv.x; acc[0][1] += av.x * bv.y; acc[0][2] += av.x * bv.z; acc[0][3] += av.x * bv.w;
            acc[1][0] += av.y * bv.x; acc[1][1] += av.y * bv.y; acc[1][2] += av.y * bv.z; acc[1][3] += av.y * bv.w;
            acc[2][0] += av.z * bv.x; acc[2][1] += av.z * bv.y; acc[2][2] += av.z * bv.z; acc[2][3] += av.z * bv.w;
            acc[3][0] += av.w * bv.x; acc[3][1] += av.w * bv.y; acc[3][2] += av.w * bv.z; acc[3][3] += av.w * bv.w;
        }
        if (next) {
            int nb = buf ^ 1;
            As[nb][lk + 0][lm] = a4n.x; As[nb][lk + 1][lm] = a4n.y;
            As[nb][lk + 2][lm] = a4n.z; As[nb][lk + 3][lm] = a4n.w;
            Bs[nb][lk + 0][lm] = bn[0]; Bs[nb][lk + 1][lm] = bn[1];
            Bs[nb][lk + 2][lm] = bn[2]; Bs[nb][lk + 3][lm] = bn[3];
            __syncthreads();
            buf = nb;
        }
    }
    int j = n0 + tx * 4;
    float bs0 = bias1[j + 0] + bias2[j + 0];
    float bs1 = bias1[j + 1] + bias2[j + 1];
    float bs2 = bias1[j + 2] + bias2[j + 2];
    float bs3 = bias1[j + 3] + bias2[j + 3];
#pragma unroll
    for (int i = 0; i < 4; i++) {
        int m = m0 + ty * 4 + i;
        float4 o;
        o.x = acc[i][0] + bs0; o.y = acc[i][1] + bs1;
        o.z = acc[i][2] + bs2; o.w = acc[i][3] + bs3;
        *(float4*)(out + (size_t)m * G4H + j) = o;
    }
}

// ---------------- LSTM step: fused recurrent GEMM + gates ------------------
// Tile: 64 batch x (16 hh x 4 gates). column c = 4*hh_i + gate; j = gate*512+hh.
__global__ __launch_bounds__(256) void lstm_step_kernel(
    const float* __restrict__ gx,   // [S*B, 2048]
    const float* __restrict__ whh,  // [2048, 512]
    float* __restrict__ hseq,       // [S*B, 512]; read row (t-1), write row t
    float* __restrict__ cst,        // [B, 512]
    int t)
{
    __shared__ __align__(16) float As[2][16][68];
    __shared__ __align__(16) float Bs[2][16][68];
    int m0  = blockIdx.x * 64;      // batch block
    int hh0 = blockIdx.y * 16;      // hh block
    int tid = threadIdx.x;
    int tx = tid & 15, ty = tid >> 4;
    float acc[4][4] = {};

    if (t > 0) {
        const float* hprev = hseq + (size_t)(t - 1) * BB * HHD;
        int lm = tid >> 2;
        int lk = (tid & 3) * 4;
        int c  = lm;
        int j  = (c & 3) * HHD + hh0 + (c >> 2);
        {
            float4 a4 = *(const float4*)(hprev + (m0 + lm) * HHD + lk);
            As[0][lk + 0][lm] = a4.x; As[0][lk + 1][lm] = a4.y;
            As[0][lk + 2][lm] = a4.z; As[0][lk + 3][lm] = a4.w;
#pragma unroll
            for (int q = 0; q < 4; q++) Bs[0][lk + q][lm] = whh[j * HHD + lk + q];
        }
        __syncthreads();
        int buf = 0;
        for (int kt = 0; kt < 32; kt++) {
            float4 a4n; float bn[4];
            bool next = (kt + 1 < 32);
            if (next) {
                int kb = (kt + 1) * 16;
                a4n = *(const float4*)(hprev + (m0 + lm) * HHD + kb + lk);
#pragma unroll
                for (int q = 0; q < 4; q++) bn[q] = whh[j * HHD + kb + lk + q];
            }
#pragma unroll
            for (int k = 0; k < 16; k++) {
                float4 av = *(const float4*)&As[buf][k][ty * 4];
                float4 bv = *(const float4*)&Bs[buf][k][tx * 4];
                acc[0][0] += av.x * bv.x; acc[0][1] += av.x * bv.y; acc[0][2] += av.x * bv.z; acc[0][3] += av.x * bv.w;
                acc[1][0] += av.y * bv.x; acc[1][1] += av.y * bv.y; acc[1][2] += av.y * bv.z; acc[1][3] += av.y * bv.w;
                acc[2][0] += av.z * bv.x; acc[2][1] += av.z * bv.y; acc[2][2] += av.z * bv.z; acc[2][3] += av.z * bv.w;
                acc[3][0] += av.w * bv.x; acc[3][1] += av.w * bv.y; acc[3][2] += av.w * bv.z; acc[3][3] += av.w * bv.w;
            }
            if (next) {
                int nb = buf ^ 1;
                As[nb][lk + 0][lm] = a4n.x; As[nb][lk + 1][lm] = a4n.y;
                As[nb][lk + 2][lm] = a4n.z; As[nb][lk + 3][lm] = a4n.w;
                Bs[nb][lk + 0][lm] = bn[0]; Bs[nb][lk + 1][lm] = bn[1];
                Bs[nb][lk + 2][lm] = bn[2]; Bs[nb][lk + 3][lm] = bn[3];
                __syncthreads();
                buf = nb;
            }
        }
    }

    // epilogue: gates + state update. acc[i][g] : i=batch sub, g=gate, hh = hh0+tx
    int hh = hh0 + tx;
    const float* gxt  = gx   + (size_t)t * BB * G4H;
    float*       hout = hseq + (size_t)t * BB * HHD;
#pragma unroll
    for (int i = 0; i < 4; i++) {
        int b = m0 + ty * 4 + i;
        float r0 = acc[i][0] + gxt[b * G4H + 0 * HHD + hh];
        float r1 = acc[i][1] + gxt[b * G4H + 1 * HHD + hh];
        float r2 = acc[i][2] + gxt[b * G4H + 2 * HHD + hh];
        float r3 = acc[i][3] + gxt[b * G4H + 3 * HHD + hh];
        float ig = 1.f / (1.f + __expf(-r0));
        float fg = 1.f / (1.f + __expf(-r1));
        float gg = tanhf(r2);
        float og = 1.f / (1.f + __expf(-r3));
        float cn = ig * gg;
        if (t > 0) cn += fg * cst[b * HHD + hh];
        cst[b * HHD + hh] = cn;
        hout[b * HHD + hh] = og * tanhf(cn);
    }
}

// ---------------- FC head: out[b,oc,n,s] = h2[s*B+b,:].fc_w[oc*207+n,:] + b --
__global__ __launch_bounds__(256) void fc_kernel(
    const float* __restrict__ A,     // g_h2 [32768, 512]
    const float* __restrict__ W,     // fc_w [414, 512]
    const float* __restrict__ bias,  // fc_b [414]
    float* __restrict__ out)         // [256, 2, 207, 128]
{
    __shared__ __align__(16) float As[2][16][68];
    __shared__ __align__(16) float Bs[2][16][68];
    int m0 = blockIdx.y * 64;
    int n0 = blockIdx.x * 64;
    int tid = threadIdx.x;
    int tx = tid & 15, ty = tid >> 4;
    int lm = tid >> 2;
    int lk = (tid & 3) * 4;
    float acc[4][4] = {};
    int jb = n0 + lm;
    bool jv = (jb < KIN);

    {
        float4 a4 = *(const float4*)(A + (size_t)(m0 + lm) * HHD + lk);
        As[0][lk + 0][lm] = a4.x; As[0][lk + 1][lm] = a4.y;
        As[0][lk + 2][lm] = a4.z; As[0][lk + 3][lm] = a4.w;
#pragma unroll
        for (int q = 0; q < 4; q++)
            Bs[0][lk + q][lm] = jv ? W[jb * HHD + lk + q] : 0.f;
    }
    __syncthreads();
    int buf = 0;
    for (int kt = 0; kt < 32; kt++) {
        float4 a4n; float bn[4];
        bool next = (kt + 1 < 32);
        if (next) {
            int kb = (kt + 1) * 16;
            a4n = *(const float4*)(A + (size_t)(m0 + lm) * HHD + kb + lk);
#pragma unroll
            for (int q = 0; q < 4; q++)
                bn[q] = jv ? W[jb * HHD + kb + lk + q] : 0.f;
        }
#pragma unroll
        for (int k = 0; k < 16; k++) {
            float4 av = *(const float4*)&As[buf][k][ty * 4];
            float4 bv = *(const float4*)&Bs[buf][k][tx * 4];
            acc[0][0] += av.x * bv.x; acc[0][1] += av.x * bv.y; acc[0][2] += av.x * bv.z; acc[0][3] += av.x * bv.w;
            acc[1][0] += av.y * bv.x; acc[1][1] += av.y * bv.y; acc[1][2] += av.y * bv.z; acc[1][3] += av.y * bv.w;
            acc[2][0] += av.z * bv.x; acc[2][1] += av.z * bv.y; acc[2][2] += av.z * bv.z; acc[2][3] += av.z * bv.w;
            acc[3][0] += av.w * bv.x; acc[3][1] += av.w * bv.y; acc[3][2] += av.w * bv.z; acc[3][3] += av.w * bv.w;
        }
        if (next) {
            int nb = buf ^ 1;
            As[nb][lk + 0][lm] = a4n.x; As[nb][lk + 1][lm] = a4n.y;
            As[nb][lk + 2][lm] = a4n.z; As[nb][lk + 3][lm] = a4n.w;
            Bs[nb][lk + 0][lm] = bn[0]; Bs[nb][lk + 1][lm] = bn[1];
            Bs[nb][lk + 2][lm] = bn[2]; Bs[nb][lk + 3][lm] = bn[3];
            __syncthreads();
            buf = nb;
        }
    }
#pragma unroll
    for (int i = 0; i < 4; i++) {
        int m = m0 + ty * 4 + i;
        int s = m >> 8;          // m = s*256 + b
        int b = m & 255;
#pragma unroll
        for (int jj = 0; jj < 4; jj++) {
            int j = n0 + tx * 4 + jj;
            if (j < KIN) {
                int oc = j / 207;
                int n  = j - oc * 207;
                out[(size_t)((b * 2 + oc) * 207 + n) * SSZ + s] = acc[i][jj] + bias[j];
            }
        }
    }
}

// ---------------- launch -----------------------------------------------------
extern "C" void kernel_launch(void* const* d_in, const int* in_sizes, int n_in,
                              void* d_out, int out_size)
{
    const float* x     = (const float*)d_in[0];
    const float* w_ih0 = (const float*)d_in[1];
    const float* w_hh0 = (const float*)d_in[2];
    const float* b_ih0 = (const float*)d_in[3];
    const float* b_hh0 = (const float*)d_in[4];
    const float* w_ih1 = (const float*)d_in[5];
    const float* w_hh1 = (const float*)d_in[6];
    const float* b_ih1 = (const float*)d_in[7];
    const float* b_hh1 = (const float*)d_in[8];
    const float* fc_w  = (const float*)d_in[9];
    const float* fc_b  = (const float*)d_in[10];
    float* out = (float*)d_out;

    float *xs, *gx, *h1, *h2, *cst;
    cudaGetSymbolAddress((void**)&xs,  g_xs);
    cudaGetSymbolAddress((void**)&gx,  g_gx);
    cudaGetSymbolAddress((void**)&h1,  g_h1);
    cudaGetSymbolAddress((void**)&h2,  g_h2);
    cudaGetSymbolAddress((void**)&cst, g_c);

    // 1) pack x -> xs [S*B, 416]
    pack_x_kernel<<<dim3(256, 13, 4), dim3(32, 8)>>>(x);

    // 2) gx = xs @ w_ih0^T + b_ih0 + b_hh0
    gemm_gx_kernel<<<dim3(G4H / 64, MTOT / 64), 256>>>(
        xs, KINP, KINP, w_ih0, KIN, KIN, b_ih0, b_hh0, gx);

    // 3) layer 1 recurrence
    for (int t = 0; t < SSZ; t++)
        lstm_step_kernel<<<dim3(BB / 64, HHD / 16), 256>>>(gx, w_hh0, h1, cst, t);

    // 4) gx = h1 @ w_ih1^T + b_ih1 + b_hh1
    gemm_gx_kernel<<<dim3(G4H / 64, MTOT / 64), 256>>>(
        h1, HHD, HHD, w_ih1, HHD, HHD, b_ih1, b_hh1, gx);

    // 5) layer 2 recurrence
    for (int t = 0; t < SSZ; t++)
        lstm_step_kernel<<<dim3(BB / 64, HHD / 16), 256>>>(gx, w_hh1, h2, cst, t);

    // 6) FC head + output transpose
    fc_kernel<<<dim3(7, MTOT / 64), 256>>>(h2, fc_w, fc_b, out);
}

// round 3
// speedup vs baseline: 1.2844x; 1.2844x over previous
#include <cuda_runtime.h>
#include <math.h>

#define BB   256      // batch
#define SSZ  128      // seq len
#define HHD  512      // hidden
#define G4H  2048     // 4*H
#define KIN  414      // F*N
#define KINP 416      // padded K for float4
#define MTOT (SSZ*BB) // 32768

typedef unsigned long long u64;

// ---------------- packed f32x2 helpers (sm_103a FFMA2) ----------------------
__device__ __forceinline__ u64 pk2(float lo, float hi) {
    u64 r; asm("mov.b64 %0, {%1, %2};" : "=l"(r) : "f"(lo), "f"(hi)); return r;
}
__device__ __forceinline__ float2 upk2(u64 v) {
    float lo, hi; asm("mov.b64 {%0, %1}, %2;" : "=f"(lo), "=f"(hi) : "l"(v));
    return make_float2(lo, hi);
}
__device__ __forceinline__ u64 ffma2(u64 a, u64 b, u64 c) {
    u64 d; asm("fma.rn.f32x2 %0, %1, %2, %3;" : "=l"(d) : "l"(a), "l"(b), "l"(c));
    return d;
}

// 4x4 outer product with packed pairs: acc[i][0]=(c0,c1), acc[i][1]=(c2,c3)
#define FMA_TILE(av, bv, acc) do { \
    u64 _b01 = pk2((bv).x, (bv).y), _b23 = pk2((bv).z, (bv).w), _a; \
    _a = pk2((av).x, (av).x); acc[0][0]=ffma2(_a,_b01,acc[0][0]); acc[0][1]=ffma2(_a,_b23,acc[0][1]); \
    _a = pk2((av).y, (av).y); acc[1][0]=ffma2(_a,_b01,acc[1][0]); acc[1][1]=ffma2(_a,_b23,acc[1][1]); \
    _a = pk2((av).z, (av).z); acc[2][0]=ffma2(_a,_b01,acc[2][0]); acc[2][1]=ffma2(_a,_b23,acc[2][1]); \
    _a = pk2((av).w, (av).w); acc[3][0]=ffma2(_a,_b01,acc[3][0]); acc[3][1]=ffma2(_a,_b23,acc[3][1]); \
} while (0)

// ---------------- scratch (device globals; no allocations allowed) ----------
__device__ __align__(256) float g_xs[MTOT * KINP];   // [S*B, 416]
__device__ __align__(256) float g_gx[MTOT * G4H];    // [S*B, 2048]
__device__ __align__(256) float g_h1[MTOT * HHD];    // layer1 hidden seq
__device__ __align__(256) float g_h2[MTOT * HHD];    // layer2 hidden seq
__device__ unsigned int g_bar;                        // grid barrier counter

__global__ void reset_bar_kernel() { g_bar = 0u; }

// ---------------- pack: x[B,F,N,S] -> xs[S*B, 416] (k = f*207+n, pad zeros) --
__global__ void pack_x_kernel(const float* __restrict__ x) {
    __shared__ float tile[32][33];
    int b  = blockIdx.x;
    int k0 = blockIdx.y * 32;
    int s0 = blockIdx.z * 32;
    int tx = threadIdx.x, ty = threadIdx.y;  // 32 x 8
    const float* xb = x + (size_t)b * KIN * SSZ;
#pragma unroll
    for (int i = 0; i < 4; i++) {
        int k = k0 + ty + 8 * i;
        if (k < KIN) tile[ty + 8 * i][tx] = xb[k * SSZ + s0 + tx];
    }
    __syncthreads();
#pragma unroll
    for (int i = 0; i < 4; i++) {
        int s = s0 + ty + 8 * i;
        int k = k0 + tx;
        if (k < KINP) {
            float v = (k < KIN) ? tile[tx][ty + 8 * i] : 0.f;
            g_xs[(s * BB + b) * KINP + k] = v;
        }
    }
}

// ---------------- big GEMM: out[m, j] = A[m,:].W[j,:] + bias1[j] + bias2[j] --
__global__ __launch_bounds__(256) void gemm_gx_kernel(
    const float* __restrict__ A, int lda, int Kpad,
    const float* __restrict__ W, int ldw, int Kw,
    const float* __restrict__ bias1, const float* __restrict__ bias2,
    float* __restrict__ out)
{
    __shared__ __align__(16) float As[2][16][68];
    __shared__ __align__(16) float Bs[2][16][68];
    int m0 = blockIdx.y * 64;
    int n0 = blockIdx.x * 64;
    int tid = threadIdx.x;
    int tx = tid & 15, ty = tid >> 4;
    int lm = tid >> 2;          // 0..63
    int lk = (tid & 3) * 4;     // 0,4,8,12
    u64 acc[4][2];
#pragma unroll
    for (int i = 0; i < 4; i++) { acc[i][0] = 0ull; acc[i][1] = 0ull; }
    int nk = Kpad / 16;
    int jb = n0 + lm;

    {   // tile 0
        float4 a4 = *(const float4*)(A + (size_t)(m0 + lm) * lda + lk);
        As[0][lk + 0][lm] = a4.x; As[0][lk + 1][lm] = a4.y;
        As[0][lk + 2][lm] = a4.z; As[0][lk + 3][lm] = a4.w;
#pragma unroll
        for (int q = 0; q < 4; q++) {
            int k = lk + q;
            Bs[0][lk + q][lm] = (k < Kw) ? W[(size_t)jb * ldw + k] : 0.f;
        }
    }
    __syncthreads();
    int buf = 0;
    for (int kt = 0; kt < nk; kt++) {
        float4 a4n; float bn[4];
        bool next = (kt + 1 < nk);
        if (next) {
            int kb = (kt + 1) * 16;
            a4n = *(const float4*)(A + (size_t)(m0 + lm) * lda + kb + lk);
#pragma unroll
            for (int q = 0; q < 4; q++) {
                int k = kb + lk + q;
                bn[q] = (k < Kw) ? W[(size_t)jb * ldw + k] : 0.f;
            }
        }
#pragma unroll
        for (int k = 0; k < 16; k++) {
            float4 av = *(const float4*)&As[buf][k][ty * 4];
            float4 bv = *(const float4*)&Bs[buf][k][tx * 4];
            FMA_TILE(av, bv, acc);
        }
        if (next) {
            int nb = buf ^ 1;
            As[nb][lk + 0][lm] = a4n.x; As[nb][lk + 1][lm] = a4n.y;
            As[nb][lk + 2][lm] = a4n.z; As[nb][lk + 3][lm] = a4n.w;
            Bs[nb][lk + 0][lm] = bn[0]; Bs[nb][lk + 1][lm] = bn[1];
            Bs[nb][lk + 2][lm] = bn[2]; Bs[nb][lk + 3][lm] = bn[3];
            __syncthreads();
            buf = nb;
        }
    }
    int j = n0 + tx * 4;
    float bs0 = bias1[j + 0] + bias2[j + 0];
    float bs1 = bias1[j + 1] + bias2[j + 1];
    float bs2 = bias1[j + 2] + bias2[j + 2];
    float bs3 = bias1[j + 3] + bias2[j + 3];
#pragma unroll
    for (int i = 0; i < 4; i++) {
        int m = m0 + ty * 4 + i;
        float2 p0 = upk2(acc[i][0]);
        float2 p1 = upk2(acc[i][1]);
        float4 o;
        o.x = p0.x + bs0; o.y = p0.y + bs1;
        o.z = p1.x + bs2; o.w = p1.y + bs3;
        *(float4*)(out + (size_t)m * G4H + j) = o;
    }
}

// ---------------- persistent LSTM recurrence (one launch per layer) ---------
// Grid: 128 CTAs (4 batch-blocks x 32 hh-blocks), 256 threads, 1 CTA/SM.
// W slice for this CTA's 64 gate-columns lives in smem for all 128 steps.
// Cell state lives in registers. Grid barrier between timesteps.
#define SMEM_PERSIST ((512 * 68 + 2 * 16 * 68) * (int)sizeof(float))

__global__ __launch_bounds__(256, 1) void lstm_persist_kernel(
    const float* __restrict__ gx,   // [S*B, 2048] (biases folded in)
    const float* __restrict__ whh,  // [2048, 512]
    float* __restrict__ hseq)       // [S*B, 512]
{
    extern __shared__ float sm[];
    float* Ws  = sm;                // [512][68]  resident W tile
    float* Asb = sm + 512 * 68;     // [2][16][68] double-buffered h tile
    const int tid = threadIdx.x;
    const int bid = blockIdx.x;
    const int m0  = (bid & 3) * 64;       // batch block
    const int hh0 = (bid >> 2) * 16;      // hh block
    const int tx = tid & 15, ty = tid >> 4;
    const int lm = tid >> 2, lk = (tid & 3) * 4;

    // stage W: column c -> gate row j = (c&3)*512 + hh0 + (c>>2)
    {
        int c = lm;
        int j = (c & 3) * HHD + hh0 + (c >> 2);
        const float* wr = whh + (size_t)j * HHD;
#pragma unroll 4
        for (int kt = 0; kt < 32; kt++) {
            float4 w4 = *(const float4*)(wr + kt * 16 + lk);
            Ws[(kt * 16 + lk + 0) * 68 + c] = w4.x;
            Ws[(kt * 16 + lk + 1) * 68 + c] = w4.y;
            Ws[(kt * 16 + lk + 2) * 68 + c] = w4.z;
            Ws[(kt * 16 + lk + 3) * 68 + c] = w4.w;
        }
    }
    __syncthreads();

    const int hh = hh0 + tx;
    float creg[4] = {0.f, 0.f, 0.f, 0.f};

    for (int t = 0; t < SSZ; t++) {
        // prefetch gx tile for this step (independent of h; latency hidden by GEMM)
        float gxr[4][4];
        const float* gxt = gx + (size_t)t * BB * G4H;
#pragma unroll
        for (int i = 0; i < 4; i++) {
            const float* p = gxt + (size_t)(m0 + ty * 4 + i) * G4H + hh;
            gxr[i][0] = __ldcg(p);
            gxr[i][1] = __ldcg(p + HHD);
            gxr[i][2] = __ldcg(p + 2 * HHD);
            gxr[i][3] = __ldcg(p + 3 * HHD);
        }

        u64 acc[4][2];
#pragma unroll
        for (int i = 0; i < 4; i++) { acc[i][0] = 0ull; acc[i][1] = 0ull; }

        if (t > 0) {
            const float* hprev = hseq + (size_t)(t - 1) * BB * HHD;
            // prologue: tile 0 of h_prev (L2-fresh via ldcg)
            float4 a4 = __ldcg((const float4*)(hprev + (size_t)(m0 + lm) * HHD + lk));
            Asb[(lk + 0) * 68 + lm] = a4.x; Asb[(lk + 1) * 68 + lm] = a4.y;
            Asb[(lk + 2) * 68 + lm] = a4.z; Asb[(lk + 3) * 68 + lm] = a4.w;
            __syncthreads();
            int buf = 0;
            for (int kt = 0; kt < 32; kt++) {
                float4 a4n;
                bool nxt = (kt + 1 < 32);
                if (nxt)
                    a4n = __ldcg((const float4*)(hprev + (size_t)(m0 + lm) * HHD + (kt + 1) * 16 + lk));
                const float* wsb = Ws + (kt * 16) * 68;
#pragma unroll
                for (int k = 0; k < 16; k++) {
                    float4 av = *(const float4*)&Asb[(buf * 16 + k) * 68 + ty * 4];
                    float4 bv = *(const float4*)&wsb[k * 68 + tx * 4];
                    FMA_TILE(av, bv, acc);
                }
                if (nxt) {
                    int nb = buf ^ 1;
                    Asb[(nb * 16 + lk + 0) * 68 + lm] = a4n.x;
                    Asb[(nb * 16 + lk + 1) * 68 + lm] = a4n.y;
                    Asb[(nb * 16 + lk + 2) * 68 + lm] = a4n.z;
                    Asb[(nb * 16 + lk + 3) * 68 + lm] = a4n.w;
                    __syncthreads();
                    buf = nb;
                }
            }
        }

        // gates + state (c in registers)
        float* hout = hseq + (size_t)t * BB * HHD;
#pragma unroll
        for (int i = 0; i < 4; i++) {
            float2 p0 = upk2(acc[i][0]);
            float2 p1 = upk2(acc[i][1]);
            float r0 = p0.x + gxr[i][0];
            float r1 = p0.y + gxr[i][1];
            float r2 = p1.x + gxr[i][2];
            float r3 = p1.y + gxr[i][3];
            float ig = 1.f / (1.f + __expf(-r0));
            float fg = 1.f / (1.f + __expf(-r1));
            float gg = tanhf(r2);
            float og = 1.f / (1.f + __expf(-r3));
            float cn = ig * gg + fg * creg[i];   // creg==0 at t==0
            creg[i] = cn;
            hout[(size_t)(m0 + ty * 4 + i) * HHD + hh] = og * tanhf(cn);
        }

        // grid barrier: release h_t to all CTAs before step t+1
        if (t + 1 < SSZ) {
            __syncthreads();
            if (tid == 0) {
                __threadfence();
                atomicAdd(&g_bar, 1u);
                unsigned tgt = (unsigned)(t + 1) * gridDim.x;
                unsigned v;
                do {
                    asm volatile("ld.global.acquire.gpu.u32 %0, [%1];" : "=r"(v) : "l"(&g_bar));
                } while (v < tgt);
            }
            __syncthreads();
        }
    }
}

// ---------------- FC head: out[b,oc,n,s] = h2[s*B+b,:].fc_w[oc*207+n,:] + b --
__global__ __launch_bounds__(256) void fc_kernel(
    const float* __restrict__ A,     // g_h2 [32768, 512]
    const float* __restrict__ W,     // fc_w [414, 512]
    const float* __restrict__ bias,  // fc_b [414]
    float* __restrict__ out)         // [256, 2, 207, 128]
{
    __shared__ __align__(16) float As[2][16][68];
    __shared__ __align__(16) float Bs[2][16][68];
    int m0 = blockIdx.y * 64;
    int n0 = blockIdx.x * 64;
    int tid = threadIdx.x;
    int tx = tid & 15, ty = tid >> 4;
    int lm = tid >> 2;
    int lk = (tid & 3) * 4;
    u64 acc[4][2];
#pragma unroll
    for (int i = 0; i < 4; i++) { acc[i][0] = 0ull; acc[i][1] = 0ull; }
    int jb = n0 + lm;
    bool jv = (jb < KIN);

    {
        float4 a4 = *(const float4*)(A + (size_t)(m0 + lm) * HHD + lk);
        As[0][lk + 0][lm] = a4.x; As[0][lk + 1][lm] = a4.y;
        As[0][lk + 2][lm] = a4.z; As[0][lk + 3][lm] = a4.w;
#pragma unroll
        for (int q = 0; q < 4; q++)
            Bs[0][lk + q][lm] = jv ? W[jb * HHD + lk + q] : 0.f;
    }
    __syncthreads();
    int buf = 0;
    for (int kt = 0; kt < 32; kt++) {
        float4 a4n; float bn[4];
        bool next = (kt + 1 < 32);
        if (next) {
            int kb = (kt + 1) * 16;
            a4n = *(const float4*)(A + (size_t)(m0 + lm) * HHD + kb + lk);
#pragma unroll
            for (int q = 0; q < 4; q++)
                bn[q] = jv ? W[jb * HHD + kb + lk + q] : 0.f;
        }
#pragma unroll
        for (int k = 0; k < 16; k++) {
            float4 av = *(const float4*)&As[buf][k][ty * 4];
            float4 bv = *(const float4*)&Bs[buf][k][tx * 4];
            FMA_TILE(av, bv, acc);
        }
        if (next) {
            int nb = buf ^ 1;
            As[nb][lk + 0][lm] = a4n.x; As[nb][lk + 1][lm] = a4n.y;
            As[nb][lk + 2][lm] = a4n.z; As[nb][lk + 3][lm] = a4n.w;
            Bs[nb][lk + 0][lm] = bn[0]; Bs[nb][lk + 1][lm] = bn[1];
            Bs[nb][lk + 2][lm] = bn[2]; Bs[nb][lk + 3][lm] = bn[3];
            __syncthreads();
            buf = nb;
        }
    }
    float accf[4][4];
#pragma unroll
    for (int i = 0; i < 4; i++) {
        float2 p0 = upk2(acc[i][0]);
        float2 p1 = upk2(acc[i][1]);
        accf[i][0] = p0.x; accf[i][1] = p0.y; accf[i][2] = p1.x; accf[i][3] = p1.y;
    }
#pragma unroll
    for (int i = 0; i < 4; i++) {
        int m = m0 + ty * 4 + i;
        int s = m >> 8;          // m = s*256 + b
        int b = m & 255;
#pragma unroll
        for (int jj = 0; jj < 4; jj++) {
            int j = n0 + tx * 4 + jj;
            if (j < KIN) {
                int oc = j / 207;
                int n  = j - oc * 207;
                out[(size_t)((b * 2 + oc) * 207 + n) * SSZ + s] = accf[i][jj] + bias[j];
            }
        }
    }
}

// ---------------- launch -----------------------------------------------------
extern "C" void kernel_launch(void* const* d_in, const int* in_sizes, int n_in,
                              void* d_out, int out_size)
{
    const float* x     = (const float*)d_in[0];
    const float* w_ih0 = (const float*)d_in[1];
    const float* w_hh0 = (const float*)d_in[2];
    const float* b_ih0 = (const float*)d_in[3];
    const float* b_hh0 = (const float*)d_in[4];
    const float* w_ih1 = (const float*)d_in[5];
    const float* w_hh1 = (const float*)d_in[6];
    const float* b_ih1 = (const float*)d_in[7];
    const float* b_hh1 = (const float*)d_in[8];
    const float* fc_w  = (const float*)d_in[9];
    const float* fc_b  = (const float*)d_in[10];
    float* out = (float*)d_out;

    float *xs, *gx, *h1, *h2;
    cudaGetSymbolAddress((void**)&xs, g_xs);
    cudaGetSymbolAddress((void**)&gx, g_gx);
    cudaGetSymbolAddress((void**)&h1, g_h1);
    cudaGetSymbolAddress((void**)&h2, g_h2);

    cudaFuncSetAttribute(lstm_persist_kernel,
                         cudaFuncAttributeMaxDynamicSharedMemorySize, SMEM_PERSIST);

    // 1) pack x -> xs [S*B, 416]
    pack_x_kernel<<<dim3(256, 13, 4), dim3(32, 8)>>>(x);

    // 2) gx = xs @ w_ih0^T + b_ih0 + b_hh0
    gemm_gx_kernel<<<dim3(G4H / 64, MTOT / 64), 256>>>(
        xs, KINP, KINP, w_ih0, KIN, KIN, b_ih0, b_hh0, gx);

    // 3) layer 1 recurrence (persistent, grid-sync per step)
    reset_bar_kernel<<<1, 1>>>();
    lstm_persist_kernel<<<128, 256, SMEM_PERSIST>>>(gx, w_hh0, h1);

    // 4) gx = h1 @ w_ih1^T + b_ih1 + b_hh1
    gemm_gx_kernel<<<dim3(G4H / 64, MTOT / 64), 256>>>(
        h1, HHD, HHD, w_ih1, HHD, HHD, b_ih1, b_hh1, gx);

    // 5) layer 2 recurrence
    reset_bar_kernel<<<1, 1>>>();
    lstm_persist_kernel<<<128, 256, SMEM_PERSIST>>>(gx, w_hh1, h2);

    // 6) FC head + output transpose
    fc_kernel<<<dim3(7, MTOT / 64), 256>>>(h2, fc_w, fc_b, out);
}